// round 12
// baseline (speedup 1.0000x reference)
#include <cuda_runtime.h>
#include <cuda_fp16.h>

#define NN 50000
#define NE 1600000
#define NB_NODE 196              // ceil(NN/256)
#define PROP_BLOCKS 1184         // 148 SMs x 8 blocks, all resident
#define PROP_WARPS (PROP_BLOCKS * 8)

typedef unsigned long long ull;

// ---------------- scratch (device globals; no allocations) ----------------
__device__ float g_degW[NN];
__device__ float g_dinv[NN];
__device__ int   g_cnt[NN];
__device__ int   g_bsum[NB_NODE];
__device__ int   g_arrive;
__device__ int   g_pbar[8];                            // per prop-step barrier counters
__device__ int   g_rowptr[NN + 2];
__device__ int   g_wp[NN];
__device__ __align__(16) unsigned g_ep4[NE];           // packed edge: lo16=src, hi16=fp16(dinv[src]*ew)
__device__ __align__(16) __half g_x16[NN * 32];        // fp16 copy of input x
__device__ __align__(16) __half g_TXh[4][NN * 32];     // Tx1..Tx4 (fp16 storage)
__device__ __align__(16) __half g_hh[NN * 32];         // layer-1 output (fp16)
__device__ __align__(16) float4 g_Wj[2][80 * 96];      // j-major splatted: [j/2][96] of {wj,wj,wj1,wj1}
__device__ float g_bp[2][96];                          // folded biases
__device__ __align__(16) float g_weff[32];             // folded head weight
__device__ float g_beff;

__device__ __forceinline__ const __half* sel_h(int sel) {
    if (sel == 9) return g_x16;
    if (sel == 4) return g_hh;
    return g_TXh[sel];
}

__device__ __forceinline__ float fsig(float x) { return 1.f / (1.f + __expf(-x)); }
__device__ __forceinline__ float ftanh(float x) {
    x = fminf(fmaxf(x, -15.f), 15.f);
    float t = __expf(2.f * x);
    return (t - 1.f) / (t + 1.f);
}

__device__ __forceinline__ __half2 u2h2(unsigned u) {
    __half2 h; *(unsigned*)&h = u; return h;
}

// ---- packed f32x2 helpers (sm_103a FFMA2 is PTX-only) ----
__device__ __forceinline__ ull pk2(float lo, float hi) {
    ull r; asm("mov.b64 %0, {%1, %2};" : "=l"(r) : "f"(lo), "f"(hi)); return r;
}
__device__ __forceinline__ ull ffma2(ull a, ull b, ull c) {
    ull d; asm("fma.rn.f32x2 %0, %1, %2, %3;" : "=l"(d) : "l"(a), "l"(b), "l"(c)); return d;
}
__device__ __forceinline__ void upk2(ull v, float& lo, float& hi) {
    asm("mov.b64 {%0, %1}, %2;" : "=f"(lo), "=f"(hi) : "l"(v));
}

// ---------------- init: zero counters + convert x to fp16 ----------------
__global__ void k_zero(const float* __restrict__ x) {
    int t = blockIdx.x * blockDim.x + threadIdx.x;
    if (t < NN) { g_degW[t] = 0.f; g_cnt[t] = 0; }
    if (t == 0) g_arrive = 0;
    if (t < 8) g_pbar[t] = 0;
    int base = t * 8;
    if (base < NN * 32) {
        float4 a = *(const float4*)(x + base);
        float4 b = *(const float4*)(x + base + 4);
        __half2* d = (__half2*)(g_x16 + base);
        d[0] = __floats2half2_rn(a.x, a.y);
        d[1] = __floats2half2_rn(a.z, a.w);
        d[2] = __floats2half2_rn(b.x, b.y);
        d[3] = __floats2half2_rn(b.z, b.w);
    }
}

__global__ void k_degree(const int* __restrict__ ei, const float* __restrict__ ew) {
    int e2 = blockIdx.x * blockDim.x + threadIdx.x;
    if (2 * e2 >= NE) return;
    int2  s = *(const int2*)(ei + 2 * e2);
    int2  d = *(const int2*)(ei + NE + 2 * e2);
    float2 w = *(const float2*)(ew + 2 * e2);
    atomicAdd(&g_degW[s.x], w.x);
    atomicAdd(&g_degW[s.y], w.y);
    atomicAdd(&g_cnt[d.x], 1);
    atomicAdd(&g_cnt[d.y], 1);
}

// dinv + hierarchical scan + rowptr, single kernel (196 blocks all resident -> safe grid barrier)
__global__ void k_mid() {
    __shared__ int sh[256];
    int t = threadIdx.x;
    int b = blockIdx.x;
    int i = b * 256 + t;
    int c = 0;
    if (i < NN) {
        float d = g_degW[i];
        g_dinv[i] = (d > 0.f) ? rsqrtf(fmaxf(d, 1e-12f)) : 0.f;
        c = g_cnt[i];
    }
    sh[t] = c;
    __syncthreads();
    for (int off = 1; off < 256; off <<= 1) {
        int v = (t >= off) ? sh[t - off] : 0;
        __syncthreads();
        sh[t] += v;
        __syncthreads();
    }
    int lexcl = sh[t] - c;
    if (t == 255) { g_bsum[b] = sh[255]; __threadfence(); }
    __syncthreads();
    if (t == 0) {
        atomicAdd(&g_arrive, 1);
        while (atomicAdd(&g_arrive, 0) < (int)gridDim.x) {}
    }
    __syncthreads();
    __threadfence();
    sh[t] = (t < NB_NODE) ? g_bsum[t] : 0;
    __syncthreads();
    for (int off = 1; off < 256; off <<= 1) {
        int v = (t >= off) ? sh[t - off] : 0;
        __syncthreads();
        sh[t] += v;
        __syncthreads();
    }
    int boff = (b == 0) ? 0 : sh[b - 1];
    int total = sh[NB_NODE - 1];
    if (i < NN) {
        int rp = boff + lexcl;
        g_rowptr[i] = rp;
        g_wp[i] = rp;
    }
    if (i == NN) { g_rowptr[NN] = total; g_rowptr[NN + 1] = total; }
}

// scatter packed 4B edges; only ONE random dinv gather (src); dst scaling folded into props
__global__ void k_scatter(const int* __restrict__ ei, const float* __restrict__ ew) {
    int e2 = blockIdx.x * blockDim.x + threadIdx.x;
    if (2 * e2 >= NE) return;
    int2  s = *(const int2*)(ei + 2 * e2);
    int2  d = *(const int2*)(ei + NE + 2 * e2);
    float2 w = *(const float2*)(ew + 2 * e2);
    float w0 = g_dinv[s.x] * w.x;
    float w1 = g_dinv[s.y] * w.y;
    int pos0 = atomicAdd(&g_wp[d.x], 1);
    int pos1 = atomicAdd(&g_wp[d.y], 1);
    unsigned v0 = (unsigned)s.x | ((unsigned)__half_as_ushort(__float2half_rn(w0)) << 16);
    unsigned v1 = (unsigned)s.y | ((unsigned)__half_as_ushort(__float2half_rn(w1)) << 16);
    g_ep4[pos0] = v0;
    g_ep4[pos1] = v1;
}

// ---------------- weight prep (both layers) + head fold, one launch ----------------
__global__ void k_prepw(const float* __restrict__ Wx0, const float* __restrict__ bx0,
                        const float* __restrict__ bh0, const float* __restrict__ bb0,
                        const float* __restrict__ Wx1, const float* __restrict__ bx1,
                        const float* __restrict__ bh1, const float* __restrict__ bb1,
                        const float* __restrict__ hw1, const float* __restrict__ hb1,
                        const float* __restrict__ hw2, const float* __restrict__ hb2,
                        const float* __restrict__ hw3, const float* __restrict__ hb3,
                        const float* __restrict__ hw4, const float* __restrict__ hb4) {
    if (blockIdx.x == 30) {
        if (blockIdx.y != 0 || threadIdx.x >= 32) return;
        int r = threadIdx.x;
        float t1r[16], t2r[8], t3r[4];
        for (int c = 0; c < 16; c++) t1r[c] = hw1[r * 16 + c];
        for (int c = 0; c < 8; c++) {
            float s = 0.f;
            for (int i = 0; i < 16; i++) s += t1r[i] * hw2[i * 8 + c];
            t2r[c] = s;
        }
        for (int c = 0; c < 4; c++) {
            float s = 0.f;
            for (int i = 0; i < 8; i++) s += t2r[i] * hw3[i * 4 + c];
            t3r[c] = s;
        }
        float we = 0.f;
        for (int i = 0; i < 4; i++) we += t3r[i] * hw4[i];
        g_weff[r] = we;
        if (r == 0) {
            float v2[8], v3[4];
            for (int c = 0; c < 8; c++) {
                float s = hb2[c];
                for (int i = 0; i < 16; i++) s += hb1[i] * hw2[i * 8 + c];
                v2[c] = s;
            }
            for (int c = 0; c < 4; c++) {
                float s = hb3[c];
                for (int i = 0; i < 8; i++) s += v2[i] * hw3[i * 4 + c];
                v3[c] = s;
            }
            float b = hb4[0];
            for (int i = 0; i < 4; i++) b += v3[i] * hw4[i];
            g_beff = b;
        }
        return;
    }
    int idx = blockIdx.x * blockDim.x + threadIdx.x;
    if (idx >= 80 * 96) return;
    int layer = blockIdx.y;
    const float* Wx = layer ? Wx1 : Wx0;
    const float* bx = layer ? bx1 : bx0;
    const float* bh = layer ? bh1 : bh0;
    const float* bb = layer ? bb1 : bb0;
    int j2 = idx / 96, o = idx % 96;
    int gi = o >> 5, f = o & 31;
    int g = (gi == 0) ? 0 : ((gi == 1) ? 2 : 3);   // gates i, c, o (forget dead: C=0)
    float w[2];
#pragma unroll
    for (int u = 0; u < 2; u++) {
        int j = 2 * j2 + u;
        int k = j >> 5, jj = j & 31;
        w[u] = Wx[(((g * 5 + k) * 32) + jj) * 32 + f];
    }
    g_Wj[layer][idx] = make_float4(w[0], w[0], w[1], w[1]);
    if (j2 == 0) g_bp[layer][o] = bx[g * 32 + f] + bh[g * 32 + f] + bb[g * 32 + f];
}

// ---------------- persistent per-layer propagation: 4 Chebyshev steps, grid barriers ----------------
// LAYER 0: input plane = x16 (sel 9).  LAYER 1: input plane = g_hh (sel 4).
template <int LAYER>
__global__ void __launch_bounds__(256, 8) k_propmega() {
    int wid = threadIdx.x >> 5;
    int lane = threadIdx.x & 31;
    int w0 = blockIdx.x * 8 + wid;
    int grp = lane >> 3;             // which of 4 edges in the quad
    int fl = (lane & 7) * 4;         // feature slot [fl..fl+3]
    const int insel0 = LAYER ? 4 : 9;
#pragma unroll 1
    for (int step = 0; step < 4; step++) {
        int insel = (step == 0) ? insel0 : (step - 1);
        const __half* xin = sel_h(insel);
        const __half* prevp = (step == 0) ? nullptr
                              : sel_h((step == 1) ? insel0 : (step - 2));
        __half* outp = g_TXh[step];
#pragma unroll 1
        for (int gw = w0; gw < NN; gw += PROP_WARPS) {
            int beg = g_rowptr[gw], end = g_rowptr[gw + 1];
            float4 acc = make_float4(0.f, 0.f, 0.f, 0.f);
            int e = beg + grp;
            if (e < end) {
                unsigned c0 = g_ep4[e];
                unsigned c1 = c0;
                if (e + 4 < end) c1 = g_ep4[e + 4];
#pragma unroll 1
                for (; e + 4 < end; e += 8) {
                    unsigned n0 = c0, n1 = c1;
                    if (e + 8 < end)  n0 = g_ep4[e + 8];
                    if (e + 12 < end) n1 = g_ep4[e + 12];
                    int s0 = (int)(c0 & 0xFFFFu);
                    int s1 = (int)(c1 & 0xFFFFu);
                    float w0f = __half2float(__ushort_as_half((unsigned short)(c0 >> 16)));
                    float w1f = __half2float(__ushort_as_half((unsigned short)(c1 >> 16)));
                    uint2 ra = *(const uint2*)(xin + s0 * 32 + fl);   // single LDG.64
                    uint2 rb = *(const uint2*)(xin + s1 * 32 + fl);
                    float2 fa0 = __half22float2(u2h2(ra.x)), fa1 = __half22float2(u2h2(ra.y));
                    float2 fb0 = __half22float2(u2h2(rb.x)), fb1 = __half22float2(u2h2(rb.y));
                    acc.x = fmaf(w0f, fa0.x, acc.x);
                    acc.y = fmaf(w0f, fa0.y, acc.y);
                    acc.z = fmaf(w0f, fa1.x, acc.z);
                    acc.w = fmaf(w0f, fa1.y, acc.w);
                    acc.x = fmaf(w1f, fb0.x, acc.x);
                    acc.y = fmaf(w1f, fb0.y, acc.y);
                    acc.z = fmaf(w1f, fb1.x, acc.z);
                    acc.w = fmaf(w1f, fb1.y, acc.w);
                    c0 = n0; c1 = n1;
                }
                if (e < end) {
                    int s0 = (int)(c0 & 0xFFFFu);
                    float w0f = __half2float(__ushort_as_half((unsigned short)(c0 >> 16)));
                    uint2 ra = *(const uint2*)(xin + s0 * 32 + fl);
                    float2 fa0 = __half22float2(u2h2(ra.x)), fa1 = __half22float2(u2h2(ra.y));
                    acc.x = fmaf(w0f, fa0.x, acc.x);
                    acc.y = fmaf(w0f, fa0.y, acc.y);
                    acc.z = fmaf(w0f, fa1.x, acc.z);
                    acc.w = fmaf(w0f, fa1.y, acc.w);
                }
            }
#pragma unroll
            for (int off = 8; off <= 16; off <<= 1) {
                acc.x += __shfl_xor_sync(0xffffffffu, acc.x, off);
                acc.y += __shfl_xor_sync(0xffffffffu, acc.y, off);
                acc.z += __shfl_xor_sync(0xffffffffu, acc.z, off);
                acc.w += __shfl_xor_sync(0xffffffffu, acc.w, off);
            }
            if (lane < 8) {
                float dn = -g_dinv[gw];          // fold dst normalization
                acc.x *= dn; acc.y *= dn; acc.z *= dn; acc.w *= dn;
                if (step > 0) {
                    const __half2* pp = (const __half2*)(prevp + gw * 32 + fl);
                    float2 p0 = __half22float2(pp[0]), p1 = __half22float2(pp[1]);
                    acc.x = 2.f * acc.x - p0.x;
                    acc.y = 2.f * acc.y - p0.y;
                    acc.z = 2.f * acc.z - p1.x;
                    acc.w = 2.f * acc.w - p1.y;
                }
                __half2* dst = (__half2*)(outp + gw * 32 + fl);
                dst[0] = __floats2half2_rn(acc.x, acc.y);
                dst[1] = __floats2half2_rn(acc.z, acc.w);
            }
        }
        if (step < 3) {                          // device-wide barrier between steps
            __syncthreads();
            __threadfence();
            if (threadIdx.x == 0) {
                int* ctr = &g_pbar[LAYER * 4 + step];
                atomicAdd(ctr, 1);
                while (atomicAdd(ctr, 0) < PROP_BLOCKS) {}
            }
            __syncthreads();
            __threadfence();
        }
    }
}

// ---------------- fused Chebyshev GEMM + gates (+ head), 16 nodes/warp ----------------
// MODE 0: write relu(h) to g_hh (fp16).  MODE 1: fold head, write out[n] (fp32).
template <int MODE>
__global__ void __launch_bounds__(128) k_gemm(int insel, int layer,
                                              const float* __restrict__ wc,
                                              float* __restrict__ out) {
    int w = threadIdx.x >> 5, lane = threadIdx.x & 31;
    int n0 = (blockIdx.x * 4 + w) * 16;
    if (n0 >= NN) return;
    const __half* planes[5];
    planes[0] = sel_h(insel);
    planes[1] = g_TXh[0]; planes[2] = g_TXh[1]; planes[3] = g_TXh[2]; planes[4] = g_TXh[3];
    const float4* Wj = g_Wj[layer];
    const float* bp = g_bp[layer];
    float b0 = bp[lane], b1 = bp[lane + 32], b2 = bp[lane + 64];
    ull acc[8][3];
#pragma unroll
    for (int p = 0; p < 8; p++) {
        acc[p][0] = pk2(b0, b0);
        acc[p][1] = pk2(b1, b1);
        acc[p][2] = pk2(b2, b2);
    }
#pragma unroll
    for (int k = 0; k < 5; k++) {
        const __half* plh = planes[k];
#pragma unroll
        for (int jj = 0; jj < 32; jj += 4) {
            int j2 = (k * 32 + jj) >> 1;
            const float4* Wp = Wj + j2 * 96 + lane;
            ulonglong2 wA0 = *(const ulonglong2*)(Wp);
            ulonglong2 wB0 = *(const ulonglong2*)(Wp + 96);
            ulonglong2 wA1 = *(const ulonglong2*)(Wp + 32);
            ulonglong2 wB1 = *(const ulonglong2*)(Wp + 96 + 32);
            ulonglong2 wA2 = *(const ulonglong2*)(Wp + 64);
            ulonglong2 wB2 = *(const ulonglong2*)(Wp + 96 + 64);
            ull w0[4] = {wA0.x, wA0.y, wB0.x, wB0.y};
            ull w1[4] = {wA1.x, wA1.y, wB1.x, wB1.y};
            ull w2[4] = {wA2.x, wA2.y, wB2.x, wB2.y};
#pragma unroll
            for (int p = 0; p < 8; p++) {
                int na = n0 + 2 * p, nb = na + 1;
                uint2 ua = *(const uint2*)(plh + na * 32 + jj);
                uint2 ub = *(const uint2*)(plh + nb * 32 + jj);
                float2 fa0 = __half22float2(u2h2(ua.x)), fa1 = __half22float2(u2h2(ua.y));
                float2 fb0 = __half22float2(u2h2(ub.x)), fb1 = __half22float2(u2h2(ub.y));
                ull q0 = pk2(fa0.x, fb0.x);
                ull q1 = pk2(fa0.y, fb0.y);
                ull q2 = pk2(fa1.x, fb1.x);
                ull q3 = pk2(fa1.y, fb1.y);
                acc[p][0] = ffma2(q0, w0[0], acc[p][0]);
                acc[p][1] = ffma2(q0, w1[0], acc[p][1]);
                acc[p][2] = ffma2(q0, w2[0], acc[p][2]);
                acc[p][0] = ffma2(q1, w0[1], acc[p][0]);
                acc[p][1] = ffma2(q1, w1[1], acc[p][1]);
                acc[p][2] = ffma2(q1, w2[1], acc[p][2]);
                acc[p][0] = ffma2(q2, w0[2], acc[p][0]);
                acc[p][1] = ffma2(q2, w1[2], acc[p][1]);
                acc[p][2] = ffma2(q2, w2[2], acc[p][2]);
                acc[p][0] = ffma2(q3, w0[3], acc[p][0]);
                acc[p][1] = ffma2(q3, w1[3], acc[p][1]);
                acc[p][2] = ffma2(q3, w2[3], acc[p][2]);
            }
        }
    }
    // ---- epilogue: gates (i, c, o), H=C=0 GConvLSTM ----
    float wc2 = wc[64 + lane];
    float we = 0.f, be = 0.f;
    if (MODE == 1) { we = g_weff[lane]; be = g_beff; }
#pragma unroll
    for (int p = 0; p < 8; p++) {
        float iv[2], cv[2], ov[2];
        upk2(acc[p][0], iv[0], iv[1]);
        upk2(acc[p][1], cv[0], cv[1]);
        upk2(acc[p][2], ov[0], ov[1]);
#pragma unroll
        for (int u = 0; u < 2; u++) {
            int n = n0 + 2 * p + u;
            float I  = fsig(iv[u]);
            float Cn = I * ftanh(cv[u]);
            float O  = fsig(ov[u] + wc2 * Cn);
            float h  = fmaxf(O * ftanh(Cn), 0.f);
            if (MODE == 0) {
                g_hh[n * 32 + lane] = __float2half_rn(h);
            } else {
                float v = h * we;
#pragma unroll
                for (int off = 16; off > 0; off >>= 1)
                    v += __shfl_xor_sync(0xffffffffu, v, off);
                if (lane == 0) out[n] = v + be;
            }
        }
    }
}

// ---------------- launch ----------------
extern "C" void kernel_launch(void* const* d_in, const int* in_sizes, int n_in,
                              void* d_out, int out_size) {
    const float* x     = (const float*)d_in[0];
    const int*   ei    = (const int*)d_in[1];
    const float* ew    = (const float*)d_in[2];
    const float* l1_Wx = (const float*)d_in[3];
    const float* l1_bx = (const float*)d_in[4];
    const float* l1_bh = (const float*)d_in[6];
    const float* l1_wc = (const float*)d_in[7];
    const float* l1_b  = (const float*)d_in[8];
    const float* l2_Wx = (const float*)d_in[9];
    const float* l2_bx = (const float*)d_in[10];
    const float* l2_bh = (const float*)d_in[12];
    const float* l2_wc = (const float*)d_in[13];
    const float* l2_b  = (const float*)d_in[14];
    const float* hw1   = (const float*)d_in[15];
    const float* hb1   = (const float*)d_in[16];
    const float* hw2   = (const float*)d_in[17];
    const float* hb2   = (const float*)d_in[18];
    const float* hw3   = (const float*)d_in[19];
    const float* hb3   = (const float*)d_in[20];
    const float* hw4   = (const float*)d_in[21];
    const float* hb4   = (const float*)d_in[22];
    float* out = (float*)d_out;

    const int NB_Z  = (NN * 32 / 8 + 255) / 256;  // 782 (zero + x->fp16)
    const int NB_E2 = (NE / 2 + 255) / 256;       // 3125 (2 edges/thread)
    const int NB_G  = (NN + 63) / 64;             // 782 (16 nodes/warp, 4 warps/block)

    // graph normalization + CSR
    k_zero<<<NB_Z, 256>>>(x);
    k_degree<<<NB_E2, 256>>>(ei, ew);
    k_mid<<<NB_NODE, 256>>>();
    k_scatter<<<NB_E2, 256>>>(ei, ew);

    // weight packing (both layers) + head folding, one launch
    dim3 gp(31, 2);
    k_prepw<<<gp, 256>>>(l1_Wx, l1_bx, l1_bh, l1_b, l2_Wx, l2_bx, l2_bh, l2_b,
                         hw1, hb1, hw2, hb2, hw3, hb3, hw4, hb4);

    // layer 1: persistent 4-step propagation, then fused GEMM+gates -> g_hh
    k_propmega<0><<<PROP_BLOCKS, 256>>>();
    k_gemm<0><<<NB_G, 128>>>(9, 0, l1_wc, out);

    // layer 2: persistent 4-step propagation, then fused GEMM+gates+head -> out
    k_propmega<1><<<PROP_BLOCKS, 256>>>();
    k_gemm<1><<<NB_G, 128>>>(4, 1, l2_wc, out);
}

// round 13
// speedup vs baseline: 1.1218x; 1.1218x over previous
#include <cuda_runtime.h>
#include <cuda_fp16.h>

#define NN 50000
#define NE 1600000
#define NB_NODE 196              // ceil(NN/256)

typedef unsigned long long ull;

struct __align__(8) EP { int s; float w; };

// ---------------- scratch (device globals; no allocations) ----------------
__device__ float g_degW[NN];
__device__ float g_dinv[NN];
__device__ int   g_cnt[NN];
__device__ int   g_bsum[NB_NODE];
__device__ int   g_arrive;
__device__ int   g_rowptr[NN + 2];
__device__ int   g_wp[NN];
__device__ __align__(16) EP g_ep[NE];
__device__ __align__(16) __half g_x16[NN * 32];        // fp16 copy of input x
__device__ __align__(16) __half g_TXh[4][NN * 32];     // Tx1..Tx4 (fp16 storage)
__device__ __align__(16) __half g_hh[NN * 32];         // layer-1 output (fp16)
__device__ __align__(16) float4 g_Wj[2][80 * 96];      // j-major splatted: [j/2][96] of {wj,wj,wj1,wj1}
__device__ float g_bp[2][96];                          // folded biases
__device__ __align__(16) float g_weff[32];             // folded head weight
__device__ float g_beff;

__device__ __forceinline__ const __half* sel_h(int sel) {
    if (sel == 9) return g_x16;
    if (sel == 4) return g_hh;
    return g_TXh[sel];
}

__device__ __forceinline__ float fsig(float x) { return 1.f / (1.f + __expf(-x)); }
__device__ __forceinline__ float ftanh(float x) {
    x = fminf(fmaxf(x, -15.f), 15.f);
    float t = __expf(2.f * x);
    return (t - 1.f) / (t + 1.f);
}

__device__ __forceinline__ __half2 u2h2(unsigned u) {
    __half2 h; *(unsigned*)&h = u; return h;
}

// ---- packed f32x2 helpers (sm_103a FFMA2 is PTX-only) ----
__device__ __forceinline__ ull pk2(float lo, float hi) {
    ull r; asm("mov.b64 %0, {%1, %2};" : "=l"(r) : "f"(lo), "f"(hi)); return r;
}
__device__ __forceinline__ ull ffma2(ull a, ull b, ull c) {
    ull d; asm("fma.rn.f32x2 %0, %1, %2, %3;" : "=l"(d) : "l"(a), "l"(b), "l"(c)); return d;
}
__device__ __forceinline__ void upk2(ull v, float& lo, float& hi) {
    asm("mov.b64 {%0, %1}, %2;" : "=f"(lo), "=f"(hi) : "l"(v));
}

// ---------------- init: zero counters + convert x to fp16 ----------------
__global__ void k_zero(const float* __restrict__ x) {
    int t = blockIdx.x * blockDim.x + threadIdx.x;
    if (t < NN) { g_degW[t] = 0.f; g_cnt[t] = 0; }
    if (t == 0) g_arrive = 0;
    int base = t * 8;
    if (base < NN * 32) {
        float4 a = *(const float4*)(x + base);
        float4 b = *(const float4*)(x + base + 4);
        __half2* d = (__half2*)(g_x16 + base);
        d[0] = __floats2half2_rn(a.x, a.y);
        d[1] = __floats2half2_rn(a.z, a.w);
        d[2] = __floats2half2_rn(b.x, b.y);
        d[3] = __floats2half2_rn(b.z, b.w);
    }
}

__global__ void k_degree(const int* __restrict__ ei, const float* __restrict__ ew) {
    int e2 = blockIdx.x * blockDim.x + threadIdx.x;
    if (2 * e2 >= NE) return;
    int2  s = *(const int2*)(ei + 2 * e2);
    int2  d = *(const int2*)(ei + NE + 2 * e2);
    float2 w = *(const float2*)(ew + 2 * e2);
    atomicAdd(&g_degW[s.x], w.x);
    atomicAdd(&g_degW[s.y], w.y);
    atomicAdd(&g_cnt[d.x], 1);
    atomicAdd(&g_cnt[d.y], 1);
}

// dinv + hierarchical scan + rowptr, single kernel (196 blocks all resident -> safe grid barrier)
__global__ void k_mid() {
    __shared__ int sh[256];
    int t = threadIdx.x;
    int b = blockIdx.x;
    int i = b * 256 + t;
    int c = 0;
    if (i < NN) {
        float d = g_degW[i];
        g_dinv[i] = (d > 0.f) ? rsqrtf(fmaxf(d, 1e-12f)) : 0.f;
        c = g_cnt[i];
    }
    sh[t] = c;
    __syncthreads();
    for (int off = 1; off < 256; off <<= 1) {
        int v = (t >= off) ? sh[t - off] : 0;
        __syncthreads();
        sh[t] += v;
        __syncthreads();
    }
    int lexcl = sh[t] - c;
    if (t == 255) { g_bsum[b] = sh[255]; __threadfence(); }
    __syncthreads();
    if (t == 0) {
        atomicAdd(&g_arrive, 1);
        while (atomicAdd(&g_arrive, 0) < (int)gridDim.x) {}
    }
    __syncthreads();
    __threadfence();
    sh[t] = (t < NB_NODE) ? g_bsum[t] : 0;
    __syncthreads();
    for (int off = 1; off < 256; off <<= 1) {
        int v = (t >= off) ? sh[t - off] : 0;
        __syncthreads();
        sh[t] += v;
        __syncthreads();
    }
    int boff = (b == 0) ? 0 : sh[b - 1];
    int total = sh[NB_NODE - 1];
    if (i < NN) {
        int rp = boff + lexcl;
        g_rowptr[i] = rp;
        g_wp[i] = rp;
    }
    if (i == NN) { g_rowptr[NN] = total; g_rowptr[NN + 1] = total; }
}

__global__ void k_scatter(const int* __restrict__ ei, const float* __restrict__ ew) {
    int e2 = blockIdx.x * blockDim.x + threadIdx.x;
    if (2 * e2 >= NE) return;
    int2  s = *(const int2*)(ei + 2 * e2);
    int2  d = *(const int2*)(ei + NE + 2 * e2);
    float2 w = *(const float2*)(ew + 2 * e2);
    int pos0 = atomicAdd(&g_wp[d.x], 1);
    EP p0; p0.s = s.x; p0.w = -g_dinv[s.x] * w.x * g_dinv[d.x];
    g_ep[pos0] = p0;
    int pos1 = atomicAdd(&g_wp[d.y], 1);
    EP p1; p1.s = s.y; p1.w = -g_dinv[s.y] * w.y * g_dinv[d.y];
    g_ep[pos1] = p1;
}

// ---------------- weight prep (both layers) + head fold, one launch ----------------
__global__ void k_prepw(const float* __restrict__ Wx0, const float* __restrict__ bx0,
                        const float* __restrict__ bh0, const float* __restrict__ bb0,
                        const float* __restrict__ Wx1, const float* __restrict__ bx1,
                        const float* __restrict__ bh1, const float* __restrict__ bb1,
                        const float* __restrict__ hw1, const float* __restrict__ hb1,
                        const float* __restrict__ hw2, const float* __restrict__ hb2,
                        const float* __restrict__ hw3, const float* __restrict__ hb3,
                        const float* __restrict__ hw4, const float* __restrict__ hb4) {
    if (blockIdx.x == 30) {
        if (blockIdx.y != 0 || threadIdx.x >= 32) return;
        int r = threadIdx.x;
        float t1r[16], t2r[8], t3r[4];
        for (int c = 0; c < 16; c++) t1r[c] = hw1[r * 16 + c];
        for (int c = 0; c < 8; c++) {
            float s = 0.f;
            for (int i = 0; i < 16; i++) s += t1r[i] * hw2[i * 8 + c];
            t2r[c] = s;
        }
        for (int c = 0; c < 4; c++) {
            float s = 0.f;
            for (int i = 0; i < 8; i++) s += t2r[i] * hw3[i * 4 + c];
            t3r[c] = s;
        }
        float we = 0.f;
        for (int i = 0; i < 4; i++) we += t3r[i] * hw4[i];
        g_weff[r] = we;
        if (r == 0) {
            float v2[8], v3[4];
            for (int c = 0; c < 8; c++) {
                float s = hb2[c];
                for (int i = 0; i < 16; i++) s += hb1[i] * hw2[i * 8 + c];
                v2[c] = s;
            }
            for (int c = 0; c < 4; c++) {
                float s = hb3[c];
                for (int i = 0; i < 8; i++) s += v2[i] * hw3[i * 4 + c];
                v3[c] = s;
            }
            float b = hb4[0];
            for (int i = 0; i < 4; i++) b += v3[i] * hw4[i];
            g_beff = b;
        }
        return;
    }
    int idx = blockIdx.x * blockDim.x + threadIdx.x;
    if (idx >= 80 * 96) return;
    int layer = blockIdx.y;
    const float* Wx = layer ? Wx1 : Wx0;
    const float* bx = layer ? bx1 : bx0;
    const float* bh = layer ? bh1 : bh0;
    const float* bb = layer ? bb1 : bb0;
    int j2 = idx / 96, o = idx % 96;
    int gi = o >> 5, f = o & 31;
    int g = (gi == 0) ? 0 : ((gi == 1) ? 2 : 3);   // gates i, c, o (forget dead: C=0)
    float w[2];
#pragma unroll
    for (int u = 0; u < 2; u++) {
        int j = 2 * j2 + u;
        int k = j >> 5, jj = j & 31;
        w[u] = Wx[(((g * 5 + k) * 32) + jj) * 32 + f];
    }
    g_Wj[layer][idx] = make_float4(w[0], w[0], w[1], w[1]);
    if (j2 == 0) g_bp[layer][o] = bx[g * 32 + f] + bh[g * 32 + f] + bb[g * 32 + f];
}

// ---------------- sparse propagation: 4 edges/warp, EP-prefetch pipeline, fp16 gathers ----------------
template <bool SUB>
__global__ void k_prop(int insel, int prevsel, int outsel) {
    int gw = (blockIdx.x * blockDim.x + threadIdx.x) >> 5;
    int lane = threadIdx.x & 31;
    if (gw >= NN) return;
    const __half* xin = sel_h(insel);
    int grp = lane >> 3;            // which of 4 edges in the quad
    int fl = (lane & 7) * 4;        // feature slot [fl..fl+3]
    int beg = g_rowptr[gw], end = g_rowptr[gw + 1];
    float4 acc = make_float4(0.f, 0.f, 0.f, 0.f);
    int e = beg + grp;
    if (e < end) {
        EP c0 = g_ep[e];
        EP c1 = c0;
        if (e + 4 < end) c1 = g_ep[e + 4];
        // pipelined: prefetch next EP pair before consuming current gathers
#pragma unroll 1
        for (; e + 4 < end; e += 8) {
            EP n0 = c0, n1 = c1;
            if (e + 8 < end)  n0 = g_ep[e + 8];
            if (e + 12 < end) n1 = g_ep[e + 12];
            uint2 ra = *(const uint2*)(xin + c0.s * 32 + fl);   // single LDG.64
            uint2 rb = *(const uint2*)(xin + c1.s * 32 + fl);
            float2 fa0 = __half22float2(u2h2(ra.x)), fa1 = __half22float2(u2h2(ra.y));
            float2 fb0 = __half22float2(u2h2(rb.x)), fb1 = __half22float2(u2h2(rb.y));
            acc.x = fmaf(c0.w, fa0.x, acc.x);
            acc.y = fmaf(c0.w, fa0.y, acc.y);
            acc.z = fmaf(c0.w, fa1.x, acc.z);
            acc.w = fmaf(c0.w, fa1.y, acc.w);
            acc.x = fmaf(c1.w, fb0.x, acc.x);
            acc.y = fmaf(c1.w, fb0.y, acc.y);
            acc.z = fmaf(c1.w, fb1.x, acc.z);
            acc.w = fmaf(c1.w, fb1.y, acc.w);
            c0 = n0; c1 = n1;
        }
        if (e < end) {
            uint2 ra = *(const uint2*)(xin + c0.s * 32 + fl);
            float2 fa0 = __half22float2(u2h2(ra.x)), fa1 = __half22float2(u2h2(ra.y));
            acc.x = fmaf(c0.w, fa0.x, acc.x);
            acc.y = fmaf(c0.w, fa0.y, acc.y);
            acc.z = fmaf(c0.w, fa1.x, acc.z);
            acc.w = fmaf(c0.w, fa1.y, acc.w);
        }
    }
#pragma unroll
    for (int off = 8; off <= 16; off <<= 1) {
        acc.x += __shfl_xor_sync(0xffffffffu, acc.x, off);
        acc.y += __shfl_xor_sync(0xffffffffu, acc.y, off);
        acc.z += __shfl_xor_sync(0xffffffffu, acc.z, off);
        acc.w += __shfl_xor_sync(0xffffffffu, acc.w, off);
    }
    if (lane < 8) {
        if (SUB) {
            const __half2* pp = (const __half2*)(sel_h(prevsel) + gw * 32 + fl);
            float2 p0 = __half22float2(pp[0]), p1 = __half22float2(pp[1]);
            acc.x = 2.f * acc.x - p0.x;
            acc.y = 2.f * acc.y - p0.y;
            acc.z = 2.f * acc.z - p1.x;
            acc.w = 2.f * acc.w - p1.y;
        }
        __half2* dst = (__half2*)(g_TXh[outsel] + gw * 32 + fl);
        dst[0] = __floats2half2_rn(acc.x, acc.y);
        dst[1] = __floats2half2_rn(acc.z, acc.w);
    }
}

// ---------------- fused Chebyshev GEMM + gates (+ head), 16 nodes/warp ----------------
// MODE 0: write relu(h) to g_hh (fp16).  MODE 1: fold head, write out[n] (fp32).
template <int MODE>
__global__ void __launch_bounds__(128) k_gemm(int insel, int layer,
                                              const float* __restrict__ wc,
                                              float* __restrict__ out) {
    int w = threadIdx.x >> 5, lane = threadIdx.x & 31;
    int n0 = (blockIdx.x * 4 + w) * 16;
    if (n0 >= NN) return;
    const __half* planes[5];
    planes[0] = sel_h(insel);
    planes[1] = g_TXh[0]; planes[2] = g_TXh[1]; planes[3] = g_TXh[2]; planes[4] = g_TXh[3];
    const float4* Wj = g_Wj[layer];
    const float* bp = g_bp[layer];
    float b0 = bp[lane], b1 = bp[lane + 32], b2 = bp[lane + 64];
    ull acc[8][3];
#pragma unroll
    for (int p = 0; p < 8; p++) {
        acc[p][0] = pk2(b0, b0);
        acc[p][1] = pk2(b1, b1);
        acc[p][2] = pk2(b2, b2);
    }
#pragma unroll
    for (int k = 0; k < 5; k++) {
        const __half* plh = planes[k];
#pragma unroll
        for (int jj = 0; jj < 32; jj += 4) {
            int j2 = (k * 32 + jj) >> 1;
            const float4* Wp = Wj + j2 * 96 + lane;
            ulonglong2 wA0 = *(const ulonglong2*)(Wp);
            ulonglong2 wB0 = *(const ulonglong2*)(Wp + 96);
            ulonglong2 wA1 = *(const ulonglong2*)(Wp + 32);
            ulonglong2 wB1 = *(const ulonglong2*)(Wp + 96 + 32);
            ulonglong2 wA2 = *(const ulonglong2*)(Wp + 64);
            ulonglong2 wB2 = *(const ulonglong2*)(Wp + 96 + 64);
            ull w0[4] = {wA0.x, wA0.y, wB0.x, wB0.y};
            ull w1[4] = {wA1.x, wA1.y, wB1.x, wB1.y};
            ull w2[4] = {wA2.x, wA2.y, wB2.x, wB2.y};
#pragma unroll
            for (int p = 0; p < 8; p++) {
                int na = n0 + 2 * p, nb = na + 1;
                uint2 ua = *(const uint2*)(plh + na * 32 + jj);
                uint2 ub = *(const uint2*)(plh + nb * 32 + jj);
                float2 fa0 = __half22float2(u2h2(ua.x)), fa1 = __half22float2(u2h2(ua.y));
                float2 fb0 = __half22float2(u2h2(ub.x)), fb1 = __half22float2(u2h2(ub.y));
                ull q0 = pk2(fa0.x, fb0.x);
                ull q1 = pk2(fa0.y, fb0.y);
                ull q2 = pk2(fa1.x, fb1.x);
                ull q3 = pk2(fa1.y, fb1.y);
                acc[p][0] = ffma2(q0, w0[0], acc[p][0]);
                acc[p][1] = ffma2(q0, w1[0], acc[p][1]);
                acc[p][2] = ffma2(q0, w2[0], acc[p][2]);
                acc[p][0] = ffma2(q1, w0[1], acc[p][0]);
                acc[p][1] = ffma2(q1, w1[1], acc[p][1]);
                acc[p][2] = ffma2(q1, w2[1], acc[p][2]);
                acc[p][0] = ffma2(q2, w0[2], acc[p][0]);
                acc[p][1] = ffma2(q2, w1[2], acc[p][1]);
                acc[p][2] = ffma2(q2, w2[2], acc[p][2]);
                acc[p][0] = ffma2(q3, w0[3], acc[p][0]);
                acc[p][1] = ffma2(q3, w1[3], acc[p][1]);
                acc[p][2] = ffma2(q3, w2[3], acc[p][2]);
            }
        }
    }
    // ---- epilogue: gates (i, c, o), H=C=0 GConvLSTM ----
    float wc2 = wc[64 + lane];
    float we = 0.f, be = 0.f;
    if (MODE == 1) { we = g_weff[lane]; be = g_beff; }
#pragma unroll
    for (int p = 0; p < 8; p++) {
        float iv[2], cv[2], ov[2];
        upk2(acc[p][0], iv[0], iv[1]);
        upk2(acc[p][1], cv[0], cv[1]);
        upk2(acc[p][2], ov[0], ov[1]);
#pragma unroll
        for (int u = 0; u < 2; u++) {
            int n = n0 + 2 * p + u;
            float I  = fsig(iv[u]);
            float Cn = I * ftanh(cv[u]);
            float O  = fsig(ov[u] + wc2 * Cn);
            float h  = fmaxf(O * ftanh(Cn), 0.f);
            if (MODE == 0) {
                g_hh[n * 32 + lane] = __float2half_rn(h);
            } else {
                float v = h * we;
#pragma unroll
                for (int off = 16; off > 0; off >>= 1)
                    v += __shfl_xor_sync(0xffffffffu, v, off);
                if (lane == 0) out[n] = v + be;
            }
        }
    }
}

// ---------------- launch ----------------
extern "C" void kernel_launch(void* const* d_in, const int* in_sizes, int n_in,
                              void* d_out, int out_size) {
    const float* x     = (const float*)d_in[0];
    const int*   ei    = (const int*)d_in[1];
    const float* ew    = (const float*)d_in[2];
    const float* l1_Wx = (const float*)d_in[3];
    const float* l1_bx = (const float*)d_in[4];
    const float* l1_bh = (const float*)d_in[6];
    const float* l1_wc = (const float*)d_in[7];
    const float* l1_b  = (const float*)d_in[8];
    const float* l2_Wx = (const float*)d_in[9];
    const float* l2_bx = (const float*)d_in[10];
    const float* l2_bh = (const float*)d_in[12];
    const float* l2_wc = (const float*)d_in[13];
    const float* l2_b  = (const float*)d_in[14];
    const float* hw1   = (const float*)d_in[15];
    const float* hb1   = (const float*)d_in[16];
    const float* hw2   = (const float*)d_in[17];
    const float* hb2   = (const float*)d_in[18];
    const float* hw3   = (const float*)d_in[19];
    const float* hb3   = (const float*)d_in[20];
    const float* hw4   = (const float*)d_in[21];
    const float* hb4   = (const float*)d_in[22];
    float* out = (float*)d_out;

    const int NB_Z  = (NN * 32 / 8 + 255) / 256;  // 782 (zero + x->fp16)
    const int NB_E2 = (NE / 2 + 255) / 256;       // 3125 (2 edges/thread)
    const int NB_W  = 6250;                       // 50000 warps / 8
    const int NB_G  = (NN + 63) / 64;             // 782 (16 nodes/warp, 4 warps/block)

    // graph normalization + CSR
    k_zero<<<NB_Z, 256>>>(x);
    k_degree<<<NB_E2, 256>>>(ei, ew);
    k_mid<<<NB_NODE, 256>>>();
    k_scatter<<<NB_E2, 256>>>(ei, ew);

    // weight packing (both layers) + head folding, one launch
    dim3 gp(31, 2);
    k_prepw<<<gp, 256>>>(l1_Wx, l1_bx, l1_bh, l1_b, l2_Wx, l2_bx, l2_bh, l2_b,
                         hw1, hb1, hw2, hb2, hw3, hb3, hw4, hb4);

    // layer 1 (input = x16, sel 9) -> g_hh (fp16)
    k_prop<false><<<NB_W, 256>>>(9, -1, 0);
    k_prop<true ><<<NB_W, 256>>>(0,  9, 1);
    k_prop<true ><<<NB_W, 256>>>(1,  0, 2);
    k_prop<true ><<<NB_W, 256>>>(2,  1, 3);
    k_gemm<0><<<NB_G, 128>>>(9, 0, l1_wc, out);

    // layer 2 (input = g_hh, sel 4) -> out (head fused)
    k_prop<false><<<NB_W, 256>>>(4, -1, 0);
    k_prop<true ><<<NB_W, 256>>>(0,  4, 1);
    k_prop<true ><<<NB_W, 256>>>(1,  0, 2);
    k_prop<true ><<<NB_W, 256>>>(2,  1, 3);
    k_gemm<1><<<NB_G, 128>>>(4, 1, l2_wc, out);
}

// round 14
// speedup vs baseline: 1.1347x; 1.0115x over previous
#include <cuda_runtime.h>
#include <cuda_fp16.h>

#define NN 50000
#define NE 1600000
#define NB_NODE 196              // ceil(NN/256)

typedef unsigned long long ull;

struct __align__(8) EP { int s; float w; };

// ---------------- scratch (device globals; no allocations) ----------------
__device__ float g_degW[NN];
__device__ float g_dinv[NN];
__device__ int   g_cnt[NN];
__device__ int   g_bsum[NB_NODE];
__device__ int   g_arrive;
__device__ int   g_rowptr[NN + 2];
__device__ int   g_wp[NN];
__device__ __align__(16) EP g_ep[NE];
__device__ __align__(16) __half g_x16[NN * 32];        // fp16 copy of input x
__device__ __align__(16) __half g_TXh[4][NN * 32];     // Tx1..Tx4 (fp16 storage)
__device__ __align__(16) __half g_hh[NN * 32];         // layer-1 output (fp16)
__device__ __align__(16) float4 g_Wj[2][80 * 96];      // j-major splatted: [j/2][96] of {wj,wj,wj1,wj1}
__device__ float g_bp[2][96];                          // folded biases
__device__ __align__(16) float g_weff[32];             // folded head weight
__device__ float g_beff;

__device__ __forceinline__ const __half* sel_h(int sel) {
    if (sel == 9) return g_x16;
    if (sel == 4) return g_hh;
    return g_TXh[sel];
}

__device__ __forceinline__ float fsig(float x) { return 1.f / (1.f + __expf(-x)); }
__device__ __forceinline__ float ftanh(float x) {
    x = fminf(fmaxf(x, -15.f), 15.f);
    float t = __expf(2.f * x);
    return (t - 1.f) / (t + 1.f);
}

__device__ __forceinline__ __half2 u2h2(unsigned u) {
    __half2 h; *(unsigned*)&h = u; return h;
}

// ---- packed f32x2 helpers (sm_103a FFMA2 is PTX-only) ----
__device__ __forceinline__ ull pk2(float lo, float hi) {
    ull r; asm("mov.b64 %0, {%1, %2};" : "=l"(r) : "f"(lo), "f"(hi)); return r;
}
__device__ __forceinline__ ull ffma2(ull a, ull b, ull c) {
    ull d; asm("fma.rn.f32x2 %0, %1, %2, %3;" : "=l"(d) : "l"(a), "l"(b), "l"(c)); return d;
}
__device__ __forceinline__ void upk2(ull v, float& lo, float& hi) {
    asm("mov.b64 {%0, %1}, %2;" : "=f"(lo), "=f"(hi) : "l"(v));
}

// ---------------- init: zero counters + convert x to fp16 ----------------
__global__ void k_zero(const float* __restrict__ x) {
    int t = blockIdx.x * blockDim.x + threadIdx.x;
    if (t < NN) { g_degW[t] = 0.f; g_cnt[t] = 0; }
    if (t == 0) g_arrive = 0;
    int base = t * 8;
    if (base < NN * 32) {
        float4 a = *(const float4*)(x + base);
        float4 b = *(const float4*)(x + base + 4);
        __half2* d = (__half2*)(g_x16 + base);
        d[0] = __floats2half2_rn(a.x, a.y);
        d[1] = __floats2half2_rn(a.z, a.w);
        d[2] = __floats2half2_rn(b.x, b.y);
        d[3] = __floats2half2_rn(b.z, b.w);
    }
}

__global__ void k_degree(const int* __restrict__ ei, const float* __restrict__ ew) {
    int e2 = blockIdx.x * blockDim.x + threadIdx.x;
    if (2 * e2 >= NE) return;
    int2  s = *(const int2*)(ei + 2 * e2);
    int2  d = *(const int2*)(ei + NE + 2 * e2);
    float2 w = *(const float2*)(ew + 2 * e2);
    atomicAdd(&g_degW[s.x], w.x);
    atomicAdd(&g_degW[s.y], w.y);
    atomicAdd(&g_cnt[d.x], 1);
    atomicAdd(&g_cnt[d.y], 1);
}

// dinv + hierarchical scan + rowptr, single kernel (196 blocks all resident -> safe grid barrier)
__global__ void k_mid() {
    __shared__ int sh[256];
    int t = threadIdx.x;
    int b = blockIdx.x;
    int i = b * 256 + t;
    int c = 0;
    if (i < NN) {
        float d = g_degW[i];
        g_dinv[i] = (d > 0.f) ? rsqrtf(fmaxf(d, 1e-12f)) : 0.f;
        c = g_cnt[i];
    }
    sh[t] = c;
    __syncthreads();
    for (int off = 1; off < 256; off <<= 1) {
        int v = (t >= off) ? sh[t - off] : 0;
        __syncthreads();
        sh[t] += v;
        __syncthreads();
    }
    int lexcl = sh[t] - c;
    if (t == 255) { g_bsum[b] = sh[255]; __threadfence(); }
    __syncthreads();
    if (t == 0) {
        atomicAdd(&g_arrive, 1);
        while (atomicAdd(&g_arrive, 0) < (int)gridDim.x) {}
    }
    __syncthreads();
    __threadfence();
    sh[t] = (t < NB_NODE) ? g_bsum[t] : 0;
    __syncthreads();
    for (int off = 1; off < 256; off <<= 1) {
        int v = (t >= off) ? sh[t - off] : 0;
        __syncthreads();
        sh[t] += v;
        __syncthreads();
    }
    int boff = (b == 0) ? 0 : sh[b - 1];
    int total = sh[NB_NODE - 1];
    if (i < NN) {
        int rp = boff + lexcl;
        g_rowptr[i] = rp;
        g_wp[i] = rp;
    }
    if (i == NN) { g_rowptr[NN] = total; g_rowptr[NN + 1] = total; }
}

__global__ void k_scatter(const int* __restrict__ ei, const float* __restrict__ ew) {
    int e2 = blockIdx.x * blockDim.x + threadIdx.x;
    if (2 * e2 >= NE) return;
    int2  s = *(const int2*)(ei + 2 * e2);
    int2  d = *(const int2*)(ei + NE + 2 * e2);
    float2 w = *(const float2*)(ew + 2 * e2);
    int pos0 = atomicAdd(&g_wp[d.x], 1);
    EP p0; p0.s = s.x; p0.w = -g_dinv[s.x] * w.x * g_dinv[d.x];
    g_ep[pos0] = p0;
    int pos1 = atomicAdd(&g_wp[d.y], 1);
    EP p1; p1.s = s.y; p1.w = -g_dinv[s.y] * w.y * g_dinv[d.y];
    g_ep[pos1] = p1;
}

// ---------------- weight prep (both layers) + head fold, one launch ----------------
__global__ void k_prepw(const float* __restrict__ Wx0, const float* __restrict__ bx0,
                        const float* __restrict__ bh0, const float* __restrict__ bb0,
                        const float* __restrict__ Wx1, const float* __restrict__ bx1,
                        const float* __restrict__ bh1, const float* __restrict__ bb1,
                        const float* __restrict__ hw1, const float* __restrict__ hb1,
                        const float* __restrict__ hw2, const float* __restrict__ hb2,
                        const float* __restrict__ hw3, const float* __restrict__ hb3,
                        const float* __restrict__ hw4, const float* __restrict__ hb4) {
    if (blockIdx.x == 30) {
        if (blockIdx.y != 0 || threadIdx.x >= 32) return;
        int r = threadIdx.x;
        float t1r[16], t2r[8], t3r[4];
        for (int c = 0; c < 16; c++) t1r[c] = hw1[r * 16 + c];
        for (int c = 0; c < 8; c++) {
            float s = 0.f;
            for (int i = 0; i < 16; i++) s += t1r[i] * hw2[i * 8 + c];
            t2r[c] = s;
        }
        for (int c = 0; c < 4; c++) {
            float s = 0.f;
            for (int i = 0; i < 8; i++) s += t2r[i] * hw3[i * 4 + c];
            t3r[c] = s;
        }
        float we = 0.f;
        for (int i = 0; i < 4; i++) we += t3r[i] * hw4[i];
        g_weff[r] = we;
        if (r == 0) {
            float v2[8], v3[4];
            for (int c = 0; c < 8; c++) {
                float s = hb2[c];
                for (int i = 0; i < 16; i++) s += hb1[i] * hw2[i * 8 + c];
                v2[c] = s;
            }
            for (int c = 0; c < 4; c++) {
                float s = hb3[c];
                for (int i = 0; i < 8; i++) s += v2[i] * hw3[i * 4 + c];
                v3[c] = s;
            }
            float b = hb4[0];
            for (int i = 0; i < 4; i++) b += v3[i] * hw4[i];
            g_beff = b;
        }
        return;
    }
    int idx = blockIdx.x * blockDim.x + threadIdx.x;
    if (idx >= 80 * 96) return;
    int layer = blockIdx.y;
    const float* Wx = layer ? Wx1 : Wx0;
    const float* bx = layer ? bx1 : bx0;
    const float* bh = layer ? bh1 : bh0;
    const float* bb = layer ? bb1 : bb0;
    int j2 = idx / 96, o = idx % 96;
    int gi = o >> 5, f = o & 31;
    int g = (gi == 0) ? 0 : ((gi == 1) ? 2 : 3);   // gates i, c, o (forget dead: C=0)
    float w[2];
#pragma unroll
    for (int u = 0; u < 2; u++) {
        int j = 2 * j2 + u;
        int k = j >> 5, jj = j & 31;
        w[u] = Wx[(((g * 5 + k) * 32) + jj) * 32 + f];
    }
    g_Wj[layer][idx] = make_float4(w[0], w[0], w[1], w[1]);
    if (j2 == 0) g_bp[layer][o] = bx[g * 32 + f] + bh[g * 32 + f] + bb[g * 32 + f];
}

// ---------------- sparse propagation: 4 edges/warp, EP-prefetch pipeline, fp16 gathers ----------------
template <bool SUB>
__global__ void k_prop(int insel, int prevsel, int outsel) {
    int gw = (blockIdx.x * blockDim.x + threadIdx.x) >> 5;
    int lane = threadIdx.x & 31;
    if (gw >= NN) return;
    const __half* xin = sel_h(insel);
    int grp = lane >> 3;            // which of 4 edges in the quad
    int fl = (lane & 7) * 4;        // feature slot [fl..fl+3]
    int beg = g_rowptr[gw], end = g_rowptr[gw + 1];
    float4 acc = make_float4(0.f, 0.f, 0.f, 0.f);
    int e = beg + grp;
    if (e < end) {
        EP c0 = g_ep[e];
        EP c1 = c0;
        if (e + 4 < end) c1 = g_ep[e + 4];
        // pipelined: prefetch next EP pair before consuming current gathers
#pragma unroll 1
        for (; e + 4 < end; e += 8) {
            EP n0 = c0, n1 = c1;
            if (e + 8 < end)  n0 = g_ep[e + 8];
            if (e + 12 < end) n1 = g_ep[e + 12];
            uint2 ra = *(const uint2*)(xin + c0.s * 32 + fl);   // single LDG.64
            uint2 rb = *(const uint2*)(xin + c1.s * 32 + fl);
            float2 fa0 = __half22float2(u2h2(ra.x)), fa1 = __half22float2(u2h2(ra.y));
            float2 fb0 = __half22float2(u2h2(rb.x)), fb1 = __half22float2(u2h2(rb.y));
            acc.x = fmaf(c0.w, fa0.x, acc.x);
            acc.y = fmaf(c0.w, fa0.y, acc.y);
            acc.z = fmaf(c0.w, fa1.x, acc.z);
            acc.w = fmaf(c0.w, fa1.y, acc.w);
            acc.x = fmaf(c1.w, fb0.x, acc.x);
            acc.y = fmaf(c1.w, fb0.y, acc.y);
            acc.z = fmaf(c1.w, fb1.x, acc.z);
            acc.w = fmaf(c1.w, fb1.y, acc.w);
            c0 = n0; c1 = n1;
        }
        if (e < end) {
            uint2 ra = *(const uint2*)(xin + c0.s * 32 + fl);
            float2 fa0 = __half22float2(u2h2(ra.x)), fa1 = __half22float2(u2h2(ra.y));
            acc.x = fmaf(c0.w, fa0.x, acc.x);
            acc.y = fmaf(c0.w, fa0.y, acc.y);
            acc.z = fmaf(c0.w, fa1.x, acc.z);
            acc.w = fmaf(c0.w, fa1.y, acc.w);
        }
    }
#pragma unroll
    for (int off = 8; off <= 16; off <<= 1) {
        acc.x += __shfl_xor_sync(0xffffffffu, acc.x, off);
        acc.y += __shfl_xor_sync(0xffffffffu, acc.y, off);
        acc.z += __shfl_xor_sync(0xffffffffu, acc.z, off);
        acc.w += __shfl_xor_sync(0xffffffffu, acc.w, off);
    }
    if (lane < 8) {
        if (SUB) {
            const __half2* pp = (const __half2*)(sel_h(prevsel) + gw * 32 + fl);
            float2 p0 = __half22float2(pp[0]), p1 = __half22float2(pp[1]);
            acc.x = 2.f * acc.x - p0.x;
            acc.y = 2.f * acc.y - p0.y;
            acc.z = 2.f * acc.z - p1.x;
            acc.w = 2.f * acc.w - p1.y;
        }
        __half2* dst = (__half2*)(g_TXh[outsel] + gw * 32 + fl);
        dst[0] = __floats2half2_rn(acc.x, acc.y);
        dst[1] = __floats2half2_rn(acc.z, acc.w);
    }
}

// ---------------- fused Chebyshev GEMM + gates (+ head), 16 nodes/warp ----------------
// MODE 0: write relu(h) to g_hh (fp16).  MODE 1: fold head, write out[n] (fp32).
template <int MODE>
__global__ void __launch_bounds__(128) k_gemm(int insel, int layer,
                                              const float* __restrict__ wc,
                                              float* __restrict__ out) {
    int w = threadIdx.x >> 5, lane = threadIdx.x & 31;
    int n0 = (blockIdx.x * 4 + w) * 16;
    if (n0 >= NN) return;
    const __half* planes[5];
    planes[0] = sel_h(insel);
    planes[1] = g_TXh[0]; planes[2] = g_TXh[1]; planes[3] = g_TXh[2]; planes[4] = g_TXh[3];
    const float4* Wj = g_Wj[layer];
    const float* bp = g_bp[layer];
    float b0 = bp[lane], b1 = bp[lane + 32], b2 = bp[lane + 64];
    ull acc[8][3];
#pragma unroll
    for (int p = 0; p < 8; p++) {
        acc[p][0] = pk2(b0, b0);
        acc[p][1] = pk2(b1, b1);
        acc[p][2] = pk2(b2, b2);
    }
#pragma unroll
    for (int k = 0; k < 5; k++) {
        const __half* plh = planes[k];
#pragma unroll
        for (int jj = 0; jj < 32; jj += 4) {
            int j2 = (k * 32 + jj) >> 1;
            const float4* Wp = Wj + j2 * 96 + lane;
            ulonglong2 wA0 = *(const ulonglong2*)(Wp);
            ulonglong2 wB0 = *(const ulonglong2*)(Wp + 96);
            ulonglong2 wA1 = *(const ulonglong2*)(Wp + 32);
            ulonglong2 wB1 = *(const ulonglong2*)(Wp + 96 + 32);
            ulonglong2 wA2 = *(const ulonglong2*)(Wp + 64);
            ulonglong2 wB2 = *(const ulonglong2*)(Wp + 96 + 64);
            ull w0[4] = {wA0.x, wA0.y, wB0.x, wB0.y};
            ull w1[4] = {wA1.x, wA1.y, wB1.x, wB1.y};
            ull w2[4] = {wA2.x, wA2.y, wB2.x, wB2.y};
#pragma unroll
            for (int p = 0; p < 8; p++) {
                int na = n0 + 2 * p, nb = na + 1;
                uint2 ua = *(const uint2*)(plh + na * 32 + jj);
                uint2 ub = *(const uint2*)(plh + nb * 32 + jj);
                float2 fa0 = __half22float2(u2h2(ua.x)), fa1 = __half22float2(u2h2(ua.y));
                float2 fb0 = __half22float2(u2h2(ub.x)), fb1 = __half22float2(u2h2(ub.y));
                ull q0 = pk2(fa0.x, fb0.x);
                ull q1 = pk2(fa0.y, fb0.y);
                ull q2 = pk2(fa1.x, fb1.x);
                ull q3 = pk2(fa1.y, fb1.y);
                acc[p][0] = ffma2(q0, w0[0], acc[p][0]);
                acc[p][1] = ffma2(q0, w1[0], acc[p][1]);
                acc[p][2] = ffma2(q0, w2[0], acc[p][2]);
                acc[p][0] = ffma2(q1, w0[1], acc[p][0]);
                acc[p][1] = ffma2(q1, w1[1], acc[p][1]);
                acc[p][2] = ffma2(q1, w2[1], acc[p][2]);
                acc[p][0] = ffma2(q2, w0[2], acc[p][0]);
                acc[p][1] = ffma2(q2, w1[2], acc[p][1]);
                acc[p][2] = ffma2(q2, w2[2], acc[p][2]);
                acc[p][0] = ffma2(q3, w0[3], acc[p][0]);
                acc[p][1] = ffma2(q3, w1[3], acc[p][1]);
                acc[p][2] = ffma2(q3, w2[3], acc[p][2]);
            }
        }
    }
    // ---- epilogue: gates (i, c, o), H=C=0 GConvLSTM ----
    float wc2 = wc[64 + lane];
    float we = 0.f, be = 0.f;
    if (MODE == 1) { we = g_weff[lane]; be = g_beff; }
#pragma unroll
    for (int p = 0; p < 8; p++) {
        float iv[2], cv[2], ov[2];
        upk2(acc[p][0], iv[0], iv[1]);
        upk2(acc[p][1], cv[0], cv[1]);
        upk2(acc[p][2], ov[0], ov[1]);
#pragma unroll
        for (int u = 0; u < 2; u++) {
            int n = n0 + 2 * p + u;
            float I  = fsig(iv[u]);
            float Cn = I * ftanh(cv[u]);
            float O  = fsig(ov[u] + wc2 * Cn);
            float h  = fmaxf(O * ftanh(Cn), 0.f);
            if (MODE == 0) {
                g_hh[n * 32 + lane] = __float2half_rn(h);
            } else {
                float v = h * we;
#pragma unroll
                for (int off = 16; off > 0; off >>= 1)
                    v += __shfl_xor_sync(0xffffffffu, v, off);
                if (lane == 0) out[n] = v + be;
            }
        }
    }
}

// ---------------- launch ----------------
extern "C" void kernel_launch(void* const* d_in, const int* in_sizes, int n_in,
                              void* d_out, int out_size) {
    const float* x     = (const float*)d_in[0];
    const int*   ei    = (const int*)d_in[1];
    const float* ew    = (const float*)d_in[2];
    const float* l1_Wx = (const float*)d_in[3];
    const float* l1_bx = (const float*)d_in[4];
    const float* l1_bh = (const float*)d_in[6];
    const float* l1_wc = (const float*)d_in[7];
    const float* l1_b  = (const float*)d_in[8];
    const float* l2_Wx = (const float*)d_in[9];
    const float* l2_bx = (const float*)d_in[10];
    const float* l2_bh = (const float*)d_in[12];
    const float* l2_wc = (const float*)d_in[13];
    const float* l2_b  = (const float*)d_in[14];
    const float* hw1   = (const float*)d_in[15];
    const float* hb1   = (const float*)d_in[16];
    const float* hw2   = (const float*)d_in[17];
    const float* hb2   = (const float*)d_in[18];
    const float* hw3   = (const float*)d_in[19];
    const float* hb3   = (const float*)d_in[20];
    const float* hw4   = (const float*)d_in[21];
    const float* hb4   = (const float*)d_in[22];
    float* out = (float*)d_out;

    const int NB_Z  = (NN * 32 / 8 + 255) / 256;  // 782 (zero + x->fp16)
    const int NB_E2 = (NE / 2 + 255) / 256;       // 3125 (2 edges/thread)
    const int NB_W  = 6250;                       // 50000 warps / 8
    const int NB_G  = (NN + 63) / 64;             // 782 (16 nodes/warp, 4 warps/block)

    // graph normalization + CSR
    k_zero<<<NB_Z, 256>>>(x);
    k_degree<<<NB_E2, 256>>>(ei, ew);
    k_mid<<<NB_NODE, 256>>>();
    k_scatter<<<NB_E2, 256>>>(ei, ew);

    // weight packing (both layers) + head folding, one launch
    dim3 gp(31, 2);
    k_prepw<<<gp, 256>>>(l1_Wx, l1_bx, l1_bh, l1_b, l2_Wx, l2_bx, l2_bh, l2_b,
                         hw1, hb1, hw2, hb2, hw3, hb3, hw4, hb4);

    // layer 1 (input = x16, sel 9) -> g_hh (fp16)
    k_prop<false><<<NB_W, 256>>>(9, -1, 0);
    k_prop<true ><<<NB_W, 256>>>(0,  9, 1);
    k_prop<true ><<<NB_W, 256>>>(1,  0, 2);
    k_prop<true ><<<NB_W, 256>>>(2,  1, 3);
    k_gemm<0><<<NB_G, 128>>>(9, 0, l1_wc, out);

    // layer 2 (input = g_hh, sel 4) -> out (head fused)
    k_prop<false><<<NB_W, 256>>>(4, -1, 0);
    k_prop<true ><<<NB_W, 256>>>(0,  4, 1);
    k_prop<true ><<<NB_W, 256>>>(1,  0, 2);
    k_prop<true ><<<NB_W, 256>>>(2,  1, 3);
    k_gemm<1><<<NB_G, 128>>>(4, 1, l2_wc, out);
}